// round 4
// baseline (speedup 1.0000x reference)
#include <cuda_runtime.h>
#include <math.h>

#define B_    8
#define N_    2048
#define H_    256
#define ROWS_ (B_ * N_)

#define BM  64
#define BK  16
#define SHS 68          // padded k-major stride for h tile (conflict-free STS, 16B-aligned rows)
#define NT  256

__device__ float g_s[ROWS_];

// ---------------------------------------------------------------------------
// Phase A: s[row] = sum_o silu( h[row,:] . W1[o,:] + b1[o] ) * w2[o]
// Tile: 64 rows x 256 cols (full o-range) x K=256 in BK=16 steps.
// 256 threads: tcol = t&31 -> 8 cols each, trow = t>>5 -> 8 rows each.
// Accumulators packed as f32x2 pairs -> fma.rn.f32x2 (2x FP32 rate on sm_100a).
// ---------------------------------------------------------------------------
__global__ void __launch_bounds__(NT, 2) s_kernel(
    const float* __restrict__ h, const float* __restrict__ W1,
    const float* __restrict__ b1, const float* __restrict__ w2)
{
    __shared__ float sH[BK * SHS];   // sH[k][row], row-contiguous
    __shared__ float sW[BK * H_];    // sW[k][col], col-contiguous
    __shared__ float red[BM * 32];   // per-(row, colgroup) partials

    const int t    = threadIdx.x;
    const int tcol = t & 31;
    const int trow = t >> 5;
    const int c0   = tcol * 8;
    const int r0   = trow * 8;
    const int rowBase = blockIdx.x * BM;

    // global->smem staging assignments
    const int hrow = t >> 2;            // 0..63
    const int hq   = (t & 3) * 4;       // k sub-offset 0,4,8,12
    const float* hp = h  + (size_t)(rowBase + hrow) * H_ + hq;
    const float* wp = W1 + (size_t)t * H_;   // thread t owns output col t

    unsigned long long acc[8][4];
#pragma unroll
    for (int r = 0; r < 8; r++)
#pragma unroll
        for (int p = 0; p < 4; p++) acc[r][p] = 0ULL;

    // prefetch tile 0
    float4 hv  = *(const float4*)(hp);
    float4 wv0 = *(const float4*)(wp + 0);
    float4 wv1 = *(const float4*)(wp + 4);
    float4 wv2 = *(const float4*)(wp + 8);
    float4 wv3 = *(const float4*)(wp + 12);

#pragma unroll 1
    for (int kt = 0; kt < H_ / BK; kt++) {
        // store staged regs -> smem (transposed to k-major)
        sH[(hq + 0) * SHS + hrow] = hv.x;
        sH[(hq + 1) * SHS + hrow] = hv.y;
        sH[(hq + 2) * SHS + hrow] = hv.z;
        sH[(hq + 3) * SHS + hrow] = hv.w;
        sW[ 0 * H_ + t] = wv0.x;  sW[ 1 * H_ + t] = wv0.y;
        sW[ 2 * H_ + t] = wv0.z;  sW[ 3 * H_ + t] = wv0.w;
        sW[ 4 * H_ + t] = wv1.x;  sW[ 5 * H_ + t] = wv1.y;
        sW[ 6 * H_ + t] = wv1.z;  sW[ 7 * H_ + t] = wv1.w;
        sW[ 8 * H_ + t] = wv2.x;  sW[ 9 * H_ + t] = wv2.y;
        sW[10 * H_ + t] = wv2.z;  sW[11 * H_ + t] = wv2.w;
        sW[12 * H_ + t] = wv3.x;  sW[13 * H_ + t] = wv3.y;
        sW[14 * H_ + t] = wv3.z;  sW[15 * H_ + t] = wv3.w;
        __syncthreads();

        // prefetch next tile (LDG latency hidden under compute below)
        if (kt + 1 < H_ / BK) {
            const int kb = (kt + 1) * BK;
            hv  = *(const float4*)(hp + kb);
            wv0 = *(const float4*)(wp + kb + 0);
            wv1 = *(const float4*)(wp + kb + 4);
            wv2 = *(const float4*)(wp + kb + 8);
            wv3 = *(const float4*)(wp + kb + 12);
        }

#pragma unroll
        for (int kk = 0; kk < BK; kk++) {
            float4 a0 = *(const float4*)&sH[kk * SHS + r0];       // broadcast within warp
            float4 a1 = *(const float4*)&sH[kk * SHS + r0 + 4];
            unsigned long long w0 = *(const unsigned long long*)&sW[kk * H_ + c0 + 0];
            unsigned long long w1 = *(const unsigned long long*)&sW[kk * H_ + c0 + 2];
            unsigned long long w2r = *(const unsigned long long*)&sW[kk * H_ + c0 + 4];
            unsigned long long w3 = *(const unsigned long long*)&sW[kk * H_ + c0 + 6];
            float av[8] = {a0.x, a0.y, a0.z, a0.w, a1.x, a1.y, a1.z, a1.w};
#pragma unroll
            for (int r = 0; r < 8; r++) {
                unsigned long long a2;
                asm("mov.b64 %0, {%1, %1};" : "=l"(a2) : "f"(av[r]));
                asm("fma.rn.f32x2 %0, %1, %2, %0;" : "+l"(acc[r][0]) : "l"(a2), "l"(w0));
                asm("fma.rn.f32x2 %0, %1, %2, %0;" : "+l"(acc[r][1]) : "l"(a2), "l"(w1));
                asm("fma.rn.f32x2 %0, %1, %2, %0;" : "+l"(acc[r][2]) : "l"(a2), "l"(w2r));
                asm("fma.rn.f32x2 %0, %1, %2, %0;" : "+l"(acc[r][3]) : "l"(a2), "l"(w3));
            }
        }
        __syncthreads();
    }

    // epilogue: + b1, SiLU, dot w2, reduce 32 col-groups
    float b1v[8], w2v[8];
#pragma unroll
    for (int c = 0; c < 8; c++) {
        b1v[c] = __ldg(b1 + c0 + c);
        w2v[c] = __ldg(w2 + c0 + c);
    }
#pragma unroll
    for (int r = 0; r < 8; r++) {
        float sp = 0.f;
#pragma unroll
        for (int p = 0; p < 4; p++) {
            float lo, hi;
            asm("mov.b64 {%0, %1}, %2;" : "=f"(lo), "=f"(hi) : "l"(acc[r][p]));
            float v0 = lo + b1v[2 * p];
            sp += (v0 / (1.f + __expf(-v0))) * w2v[2 * p];
            float v1 = hi + b1v[2 * p + 1];
            sp += (v1 / (1.f + __expf(-v1))) * w2v[2 * p + 1];
        }
        red[(r0 + r) * 32 + tcol] = sp;
    }
    __syncthreads();
    if (t < BM) {
        float s = 0.f;
        const float* rr = &red[t * 32];
#pragma unroll
        for (int g = 0; g < 32; g++) s += rr[g];
        g_s[rowBase + t] = s;
    }
}

// ---------------------------------------------------------------------------
// Phase B: out[b,i,j] = truncf( (s[b,i] + b2) - s[b,j] )  stored as FLOAT.
// (reference .astype(int64) truncates toward zero; harness output dtype is
// float32, so we store the truncated value as a float.)
// One block per (i,b) row; each thread writes 8 consecutive j (2 x STG.128).
// Pure HBM-write-bound: 134 MB.
// ---------------------------------------------------------------------------
__global__ void __launch_bounds__(NT) out_kernel(
    const float* __restrict__ b2p, float* __restrict__ out)
{
    const int t = threadIdx.x;
    const int i = blockIdx.x;
    const int b = blockIdx.y;
    if (i >= N_ || b >= B_) return;
    const float* sb = g_s + b * N_;
    const float sib = sb[i] + __ldg(b2p);
    const int j0 = t * 8;
    float4 p0 = *(const float4*)(sb + j0);
    float4 p1 = *(const float4*)(sb + j0 + 4);
    float4 v0, v1;
    v0.x = truncf(sib - p0.x);  v0.y = truncf(sib - p0.y);
    v0.z = truncf(sib - p0.z);  v0.w = truncf(sib - p0.w);
    v1.x = truncf(sib - p1.x);  v1.y = truncf(sib - p1.y);
    v1.z = truncf(sib - p1.z);  v1.w = truncf(sib - p1.w);
    const size_t base = ((size_t)(b * N_ + i)) * N_ + j0;
    *(float4*)(out + base)     = v0;
    *(float4*)(out + base + 4) = v1;
}

extern "C" void kernel_launch(void* const* d_in, const int* in_sizes, int n_in,
                              void* d_out, int out_size)
{
    // Identify inputs by element count (order: h, node_mask, n_nodes, W1, b1, w2, b2)
    const float *h = 0, *W1 = 0, *b1 = 0, *w2 = 0, *b2 = 0;
    for (int idx = 0; idx < n_in; ++idx) {
        const int sz = in_sizes[idx];
        if (sz == ROWS_ * H_)      h  = (const float*)d_in[idx];
        else if (sz == H_ * H_)    W1 = (const float*)d_in[idx];
        else if (sz == H_) {       // first size-256 input = b1, second = w2
            if (!b1) b1 = (const float*)d_in[idx];
            else if (!w2) w2 = (const float*)d_in[idx];
        }
        else if (sz == 1)          b2 = (const float*)d_in[idx]; // scalar b2
        // sz == ROWS_ (node_mask): all-ones, unused by the math
    }
    (void)out_size;

    s_kernel<<<ROWS_ / BM, NT>>>(h, W1, b1, w2);
    out_kernel<<<dim3(N_, B_), NT>>>(b2, (float*)d_out);
}

// round 5
// speedup vs baseline: 1.0613x; 1.0613x over previous
#include <cuda_runtime.h>
#include <math.h>

#define B_    8
#define N_    2048
#define H_    256
#define ROWS_ (B_ * N_)

#define BM  64
#define BK  16
#define SHS 68          // padded k-major stride for h tile (conflict-free STS)
#define NT  256
#define IPB 4           // out_kernel: i-rows per block

__device__ float g_s[ROWS_];

// ---------------------------------------------------------------------------
// Phase A: s[row] = sum_o silu( h[row,:] . W1[o,:] + b1[o] ) * w2[o]
// 64 rows x 256 cols x K=256 (BK=16 steps). 256 threads.
// Column map per thread: pairs {2*tcol, 2*tcol+1} in 4 groups offset 0/64/128/192
// -> sW LDS.64 is lane-contiguous (8B stride) = conflict-free.
// Accumulators are f32x2 packed -> fma.rn.f32x2 (2x FP32 rate).
// ---------------------------------------------------------------------------
__global__ void __launch_bounds__(NT, 2) s_kernel(
    const float* __restrict__ h, const float* __restrict__ W1,
    const float* __restrict__ b1, const float* __restrict__ w2)
{
    __shared__ float sH[BK * SHS];   // sH[k][row]
    __shared__ float sW[BK * H_];    // sW[k][col]
    __shared__ float red[BM * 32];   // per-(row, colgroup) partials

    const int t    = threadIdx.x;
    const int tcol = t & 31;
    const int trow = t >> 5;
    const int cp   = tcol * 2;       // column pair base within each 64-col group
    const int r0   = trow * 8;
    const int rowBase = blockIdx.x * BM;

    const int hrow = t >> 2;            // 0..63
    const int hq   = (t & 3) * 4;       // k sub-offset 0,4,8,12
    const float* hp = h  + (size_t)(rowBase + hrow) * H_ + hq;
    const float* wp = W1 + (size_t)t * H_;   // thread t stages output col t

    unsigned long long acc[8][4];
#pragma unroll
    for (int r = 0; r < 8; r++)
#pragma unroll
        for (int g = 0; g < 4; g++) acc[r][g] = 0ULL;

    // prefetch tile 0
    float4 hv  = *(const float4*)(hp);
    float4 wv0 = *(const float4*)(wp + 0);
    float4 wv1 = *(const float4*)(wp + 4);
    float4 wv2 = *(const float4*)(wp + 8);
    float4 wv3 = *(const float4*)(wp + 12);

#pragma unroll 1
    for (int kt = 0; kt < H_ / BK; kt++) {
        sH[(hq + 0) * SHS + hrow] = hv.x;
        sH[(hq + 1) * SHS + hrow] = hv.y;
        sH[(hq + 2) * SHS + hrow] = hv.z;
        sH[(hq + 3) * SHS + hrow] = hv.w;
        sW[ 0 * H_ + t] = wv0.x;  sW[ 1 * H_ + t] = wv0.y;
        sW[ 2 * H_ + t] = wv0.z;  sW[ 3 * H_ + t] = wv0.w;
        sW[ 4 * H_ + t] = wv1.x;  sW[ 5 * H_ + t] = wv1.y;
        sW[ 6 * H_ + t] = wv1.z;  sW[ 7 * H_ + t] = wv1.w;
        sW[ 8 * H_ + t] = wv2.x;  sW[ 9 * H_ + t] = wv2.y;
        sW[10 * H_ + t] = wv2.z;  sW[11 * H_ + t] = wv2.w;
        sW[12 * H_ + t] = wv3.x;  sW[13 * H_ + t] = wv3.y;
        sW[14 * H_ + t] = wv3.z;  sW[15 * H_ + t] = wv3.w;
        __syncthreads();

        if (kt + 1 < H_ / BK) {
            const int kb = (kt + 1) * BK;
            hv  = *(const float4*)(hp + kb);
            wv0 = *(const float4*)(wp + kb + 0);
            wv1 = *(const float4*)(wp + kb + 4);
            wv2 = *(const float4*)(wp + kb + 8);
            wv3 = *(const float4*)(wp + kb + 12);
        }

#pragma unroll
        for (int kk = 0; kk < BK; kk++) {
            float4 a0 = *(const float4*)&sH[kk * SHS + r0];       // warp-uniform broadcast
            float4 a1 = *(const float4*)&sH[kk * SHS + r0 + 4];
            const float* wrow = &sW[kk * H_ + cp];
            unsigned long long w0 = *(const unsigned long long*)(wrow + 0);    // lanes contiguous
            unsigned long long w1 = *(const unsigned long long*)(wrow + 64);
            unsigned long long w2r = *(const unsigned long long*)(wrow + 128);
            unsigned long long w3 = *(const unsigned long long*)(wrow + 192);
            float av[8] = {a0.x, a0.y, a0.z, a0.w, a1.x, a1.y, a1.z, a1.w};
#pragma unroll
            for (int r = 0; r < 8; r++) {
                unsigned long long a2;
                asm("mov.b64 %0, {%1, %1};" : "=l"(a2) : "f"(av[r]));
                asm("fma.rn.f32x2 %0, %1, %2, %0;" : "+l"(acc[r][0]) : "l"(a2), "l"(w0));
                asm("fma.rn.f32x2 %0, %1, %2, %0;" : "+l"(acc[r][1]) : "l"(a2), "l"(w1));
                asm("fma.rn.f32x2 %0, %1, %2, %0;" : "+l"(acc[r][2]) : "l"(a2), "l"(w2r));
                asm("fma.rn.f32x2 %0, %1, %2, %0;" : "+l"(acc[r][3]) : "l"(a2), "l"(w3));
            }
        }
        __syncthreads();
    }

    // epilogue: + b1, SiLU, dot w2, reduce 32 col-groups per row
    float b1v[4][2], w2v[4][2];
#pragma unroll
    for (int g = 0; g < 4; g++) {
        const int c = g * 64 + cp;
        b1v[g][0] = __ldg(b1 + c);     b1v[g][1] = __ldg(b1 + c + 1);
        w2v[g][0] = __ldg(w2 + c);     w2v[g][1] = __ldg(w2 + c + 1);
    }
#pragma unroll
    for (int r = 0; r < 8; r++) {
        float sp = 0.f;
#pragma unroll
        for (int g = 0; g < 4; g++) {
            float lo, hi;
            asm("mov.b64 {%0, %1}, %2;" : "=f"(lo), "=f"(hi) : "l"(acc[r][g]));
            float v0 = lo + b1v[g][0];
            sp += (v0 / (1.f + __expf(-v0))) * w2v[g][0];
            float v1 = hi + b1v[g][1];
            sp += (v1 / (1.f + __expf(-v1))) * w2v[g][1];
        }
        red[(r0 + r) * 32 + tcol] = sp;
    }
    __syncthreads();
    if (t < BM) {
        float s = 0.f;
        const float* rr = &red[t * 32];
#pragma unroll
        for (int g = 0; g < 32; g++) s += rr[g];
        g_s[rowBase + t] = s;
    }
}

// ---------------------------------------------------------------------------
// Phase B: out[b,i,j] = truncf( (s[b,i] + b2) - s[b,j] ) stored as float.
// IPB=4 i-rows per block: s_j loaded once per thread, reused for 4 rows
// (cuts L1 load wavefronts 4x). Streaming stores (.cs) — output never re-read.
// ---------------------------------------------------------------------------
__global__ void __launch_bounds__(NT) out_kernel(
    const float* __restrict__ b2p, float* __restrict__ out)
{
    const int t  = threadIdx.x;
    const int i0 = blockIdx.x * IPB;
    const int b  = blockIdx.y;
    const float* sb = g_s + b * N_;
    const float b2 = __ldg(b2p);

    const int j0 = t * 8;
    float4 p0 = *(const float4*)(sb + j0);
    float4 p1 = *(const float4*)(sb + j0 + 4);

    float si[IPB];
#pragma unroll
    for (int r = 0; r < IPB; r++) si[r] = sb[i0 + r] + b2;

#pragma unroll
    for (int r = 0; r < IPB; r++) {
        float4 v0, v1;
        v0.x = truncf(si[r] - p0.x);  v0.y = truncf(si[r] - p0.y);
        v0.z = truncf(si[r] - p0.z);  v0.w = truncf(si[r] - p0.w);
        v1.x = truncf(si[r] - p1.x);  v1.y = truncf(si[r] - p1.y);
        v1.z = truncf(si[r] - p1.z);  v1.w = truncf(si[r] - p1.w);
        float* dst = out + ((size_t)(b * N_ + i0 + r)) * N_ + j0;
        __stcs((float4*)dst,       v0);
        __stcs((float4*)(dst + 4), v1);
    }
}

extern "C" void kernel_launch(void* const* d_in, const int* in_sizes, int n_in,
                              void* d_out, int out_size)
{
    // Identify inputs by element count (order: h, node_mask, n_nodes, W1, b1, w2, b2)
    const float *h = 0, *W1 = 0, *b1 = 0, *w2 = 0, *b2 = 0;
    for (int idx = 0; idx < n_in; ++idx) {
        const int sz = in_sizes[idx];
        if (sz == ROWS_ * H_)      h  = (const float*)d_in[idx];
        else if (sz == H_ * H_)    W1 = (const float*)d_in[idx];
        else if (sz == H_) {       // first size-256 input = b1, second = w2
            if (!b1) b1 = (const float*)d_in[idx];
            else if (!w2) w2 = (const float*)d_in[idx];
        }
        else if (sz == 1)          b2 = (const float*)d_in[idx];
        // sz == ROWS_ (node_mask): all-ones, unused
    }
    (void)out_size;

    s_kernel<<<ROWS_ / BM, NT>>>(h, W1, b1, w2);
    out_kernel<<<dim3(N_ / IPB, B_), NT>>>(b2, (float*)d_out);
}

// round 8
// speedup vs baseline: 1.3201x; 1.2439x over previous
#include <cuda_runtime.h>
#include <cuda_bf16.h>
#include <math.h>
#include <stdint.h>

#define B_    8
#define N_    2048
#define H_    256
#define ROWS_ (B_ * N_)
#define NT    256

// ---------------- device scratch (static; no allocs allowed) ----------------
__device__ float g_s[ROWS_];
__device__ float g_sp[4][ROWS_];                                    // per-o-block partials
__device__ __align__(16) __nv_bfloat16 gH[2][(size_t)ROWS_ * H_];   // 2 x 8 MB limbs
__device__ __align__(16) __nv_bfloat16 gW[2][H_ * H_];              // 2 x 128 KB limbs

// ---------------- warp-mma helpers ----------------
__device__ __forceinline__ uint32_t smem_u32(const void* p) {
    uint32_t a;
    asm("{ .reg .u64 t; cvta.to.shared.u64 t, %1; cvt.u32.u64 %0, t; }" : "=r"(a) : "l"(p));
    return a;
}
__device__ __forceinline__ void ldm4(uint32_t* r, uint32_t addr) {
    asm volatile("ldmatrix.sync.aligned.m8n8.x4.shared.b16 {%0,%1,%2,%3}, [%4];"
                 : "=r"(r[0]), "=r"(r[1]), "=r"(r[2]), "=r"(r[3]) : "r"(addr));
}
__device__ __forceinline__ void mma16816(float* c, const uint32_t* a, const uint32_t* b) {
    asm volatile(
        "mma.sync.aligned.m16n8k16.row.col.f32.bf16.bf16.f32 "
        "{%0,%1,%2,%3},{%4,%5,%6,%7},{%8,%9},{%0,%1,%2,%3};"
        : "+f"(c[0]), "+f"(c[1]), "+f"(c[2]), "+f"(c[3])
        : "r"(a[0]), "r"(a[1]), "r"(a[2]), "r"(a[3]), "r"(b[0]), "r"(b[1]));
}

// ---------------- conversion: fp32 -> 2 bf16 limbs ----------------
__device__ __forceinline__ void split2(float x, __nv_bfloat16& a, __nv_bfloat16& b) {
    a = __float2bfloat16(x);
    b = __float2bfloat16(x - __bfloat162float(a));
}
__global__ void __launch_bounds__(NT) conv_kernel(const float* __restrict__ src,
                                                  int n2, int which) {
    int i = blockIdx.x * NT + threadIdx.x;
    if (i >= n2) return;
    float2 v = ((const float2*)src)[i];
    __nv_bfloat16 a0, b0, a1, b1;
    split2(v.x, a0, b0);
    split2(v.y, a1, b1);
    if (which == 0) {
        *(__nv_bfloat162*)&gH[0][i * 2] = __nv_bfloat162(a0, a1);
        *(__nv_bfloat162*)&gH[1][i * 2] = __nv_bfloat162(b0, b1);
    } else {
        *(__nv_bfloat162*)&gW[0][i * 2] = __nv_bfloat162(a0, a1);
        *(__nv_bfloat162*)&gW[1][i * 2] = __nv_bfloat162(b0, b1);
    }
}

// ---------------- Phase A: mma.sync bf16 2-limb GEMM + fused epilogue -------
// Block: 128 threads (4 warps). Tile M=128 rows x N=64 cols, K=256 in 4x64.
// Warp tile 32x64: 2 m-tiles(16) x 8 n-tiles(8), 3 limb-products per mma pos.
// smem: A[2][128][72] halves, B[2][64][72] halves (stride 72 = 144B -> each
// 8-row ldmatrix footprint covers 8 distinct 16B bank groups: conflict-free).
// Partial s (this o-block) -> g_sp[blockIdx.y].
#define AST    72
#define A_LIMB (128 * AST)          // halves
#define B_LIMB (64 * AST)
#define SA_BYTES (2 * A_LIMB * 2)   // 36864
#define SB_BASE  SA_BYTES
#define SMEMSZ (SA_BYTES + 2 * B_LIMB * 2)   // 55296

__global__ void __launch_bounds__(128, 2) mma_kernel(
    const float* __restrict__ b1, const float* __restrict__ w2)
{
    extern __shared__ char smem[];
    const uint32_t sb = smem_u32(smem);
    const int t = threadIdx.x, wid = t >> 5, lane = t & 31;
    const int rowBase = blockIdx.x * 128;
    const int colBase = blockIdx.y * 64;

    // ldmatrix lane addresses (bytes)
    uint32_t aaddr[2][2], baddr[2][4];
    {
        int arow = lane & 15, acg = lane >> 4;
#pragma unroll
        for (int s = 0; s < 2; s++)
#pragma unroll
            for (int mt = 0; mt < 2; mt++)
                aaddr[s][mt] = sb + (s * A_LIMB + (wid * 32 + mt * 16 + arow) * AST + acg * 8) * 2;
        int brow = (lane & 7) + 8 * (lane >> 4), bcg = (lane >> 3) & 1;
#pragma unroll
        for (int s = 0; s < 2; s++)
#pragma unroll
            for (int np = 0; np < 4; np++)
                baddr[s][np] = sb + SB_BASE + (s * B_LIMB + (np * 16 + brow) * AST + bcg * 8) * 2;
    }

    float acc[2][8][4];
#pragma unroll
    for (int mt = 0; mt < 2; mt++)
#pragma unroll
        for (int nt = 0; nt < 8; nt++)
#pragma unroll
            for (int e = 0; e < 4; e++) acc[mt][nt][e] = 0.f;

    // ---- stage chunk 0 ----
#pragma unroll
    for (int s = 0; s < 2; s++) {
#pragma unroll
        for (int u = t; u < 1024; u += 128) {
            int row = u >> 3, q = u & 7;
            uint4 v = *(const uint4*)&gH[s][(size_t)(rowBase + row) * H_ + q * 8];
            *(uint4*)(smem + (s * A_LIMB + row * AST + q * 8) * 2) = v;
        }
#pragma unroll
        for (int u = t; u < 512; u += 128) {
            int row = u >> 3, q = u & 7;
            uint4 v = *(const uint4*)&gW[s][(size_t)(colBase + row) * H_ + q * 8];
            *(uint4*)(smem + SB_BASE + (s * B_LIMB + row * AST + q * 8) * 2) = v;
        }
    }
    __syncthreads();

#pragma unroll 1
    for (int kc = 0; kc < 4; kc++) {
#pragma unroll
        for (int ks = 0; ks < 4; ks++) {
            uint32_t a[2][2][4];
#pragma unroll
            for (int s = 0; s < 2; s++)
#pragma unroll
                for (int mt = 0; mt < 2; mt++)
                    ldm4(a[s][mt], aaddr[s][mt] + ks * 32);
            uint32_t b[2][8][2];
#pragma unroll
            for (int s = 0; s < 2; s++)
#pragma unroll
                for (int np = 0; np < 4; np++) {
                    uint32_t r[4];
                    ldm4(r, baddr[s][np] + ks * 32);
                    b[s][np * 2][0] = r[0];  b[s][np * 2][1] = r[1];
                    b[s][np * 2 + 1][0] = r[2];  b[s][np * 2 + 1][1] = r[3];
                }
#pragma unroll
            for (int mt = 0; mt < 2; mt++)
#pragma unroll
                for (int nt = 0; nt < 8; nt++) {
                    mma16816(acc[mt][nt], a[0][mt], b[0][nt]);   // hi*hi
                    mma16816(acc[mt][nt], a[0][mt], b[1][nt]);   // hi*lo
                    mma16816(acc[mt][nt], a[1][mt], b[0][nt]);   // lo*hi
                }
        }
        __syncthreads();
        if (kc < 3) {
            const int ko = (kc + 1) * 64;
#pragma unroll
            for (int s = 0; s < 2; s++) {
#pragma unroll
                for (int u = t; u < 1024; u += 128) {
                    int row = u >> 3, q = u & 7;
                    uint4 v = *(const uint4*)&gH[s][(size_t)(rowBase + row) * H_ + ko + q * 8];
                    *(uint4*)(smem + (s * A_LIMB + row * AST + q * 8) * 2) = v;
                }
#pragma unroll
                for (int u = t; u < 512; u += 128) {
                    int row = u >> 3, q = u & 7;
                    uint4 v = *(const uint4*)&gW[s][(size_t)(colBase + row) * H_ + ko + q * 8];
                    *(uint4*)(smem + SB_BASE + (s * B_LIMB + row * AST + q * 8) * 2) = v;
                }
            }
            __syncthreads();
        }
    }

    // ---- epilogue: silu(x+b1)*w2, reduce to per-row partial for this o-block
    float bb[8][2], ww[8][2];
#pragma unroll
    for (int nt = 0; nt < 8; nt++) {
        int c0 = colBase + nt * 8 + 2 * (lane & 3);
        bb[nt][0] = __ldg(b1 + c0);     bb[nt][1] = __ldg(b1 + c0 + 1);
        ww[nt][0] = __ldg(w2 + c0);     ww[nt][1] = __ldg(w2 + c0 + 1);
    }
#pragma unroll
    for (int mt = 0; mt < 2; mt++) {
        float p0 = 0.f, p1 = 0.f;
#pragma unroll
        for (int nt = 0; nt < 8; nt++) {
            float v;
            v = acc[mt][nt][0] + bb[nt][0];  p0 += (v / (1.f + __expf(-v))) * ww[nt][0];
            v = acc[mt][nt][1] + bb[nt][1];  p0 += (v / (1.f + __expf(-v))) * ww[nt][1];
            v = acc[mt][nt][2] + bb[nt][0];  p1 += (v / (1.f + __expf(-v))) * ww[nt][0];
            v = acc[mt][nt][3] + bb[nt][1];  p1 += (v / (1.f + __expf(-v))) * ww[nt][1];
        }
        p0 += __shfl_xor_sync(0xFFFFFFFF, p0, 1);
        p0 += __shfl_xor_sync(0xFFFFFFFF, p0, 2);
        p1 += __shfl_xor_sync(0xFFFFFFFF, p1, 1);
        p1 += __shfl_xor_sync(0xFFFFFFFF, p1, 2);
        if ((lane & 3) == 0) {
            int row = rowBase + wid * 32 + mt * 16 + (lane >> 2);
            g_sp[blockIdx.y][row] = p0;
            g_sp[blockIdx.y][row + 8] = p1;
        }
    }
}

// ---------------- deterministic partial sum: g_s = sum of 4 o-block parts ---
__global__ void __launch_bounds__(NT) sum_kernel() {
    int i = blockIdx.x * NT + threadIdx.x;
    g_s[i] = (g_sp[0][i] + g_sp[1][i]) + (g_sp[2][i] + g_sp[3][i]);
}

// ---------------- Phase B: out[b,i,j] = truncf(s_i - s_j + b2) as float -----
__global__ void __launch_bounds__(NT) out_kernel(
    const float* __restrict__ b2p, float* __restrict__ out)
{
    const int t = threadIdx.x;
    const int i = blockIdx.x;
    const int b = blockIdx.y;
    const float* sbp = g_s + b * N_;
    const float sib = sbp[i] + __ldg(b2p);
    const int j0 = t * 8;
    float4 p0 = *(const float4*)(sbp + j0);
    float4 p1 = *(const float4*)(sbp + j0 + 4);
    float4 v0, v1;
    v0.x = truncf(sib - p0.x);  v0.y = truncf(sib - p0.y);
    v0.z = truncf(sib - p0.z);  v0.w = truncf(sib - p0.w);
    v1.x = truncf(sib - p1.x);  v1.y = truncf(sib - p1.y);
    v1.z = truncf(sib - p1.z);  v1.w = truncf(sib - p1.w);
    const size_t base = ((size_t)(b * N_ + i)) * N_ + j0;
    *(float4*)(out + base)     = v0;
    *(float4*)(out + base + 4) = v1;
}

extern "C" void kernel_launch(void* const* d_in, const int* in_sizes, int n_in,
                              void* d_out, int out_size)
{
    const float *h = 0, *W1 = 0, *b1 = 0, *w2 = 0, *b2 = 0;
    for (int idx = 0; idx < n_in; ++idx) {
        const int sz = in_sizes[idx];
        if (sz == ROWS_ * H_)      h  = (const float*)d_in[idx];
        else if (sz == H_ * H_)    W1 = (const float*)d_in[idx];
        else if (sz == H_) {
            if (!b1) b1 = (const float*)d_in[idx];
            else if (!w2) w2 = (const float*)d_in[idx];
        }
        else if (sz == 1)          b2 = (const float*)d_in[idx];
    }
    (void)out_size;

    static int attr_set = 0;
    if (!attr_set) {
        cudaFuncSetAttribute(mma_kernel, cudaFuncAttributeMaxDynamicSharedMemorySize, SMEMSZ);
        attr_set = 1;
    }

    conv_kernel<<<(H_ * H_ / 2 + NT - 1) / NT, NT>>>(W1, H_ * H_ / 2, 1);
    conv_kernel<<<(ROWS_ * H_ / 2 + NT - 1) / NT, NT>>>(h, ROWS_ * H_ / 2, 0);
    mma_kernel<<<dim3(ROWS_ / 128, 4), 128, SMEMSZ>>>(b1, w2);
    sum_kernel<<<ROWS_ / NT, NT>>>();
    out_kernel<<<dim3(N_, B_), NT>>>(b2, (float*)d_out);
}

// round 9
// speedup vs baseline: 1.3526x; 1.0246x over previous
#include <cuda_runtime.h>
#include <cuda_bf16.h>
#include <math.h>
#include <stdint.h>

#define B_    8
#define N_    2048
#define H_    256
#define ROWS_ (B_ * N_)
#define NT    256
#define NW2   (H_ * H_ / 2)
#define NH2   (ROWS_ * H_ / 2)

// ---------------- device scratch (static; no allocs allowed) ----------------
__device__ float g_s[ROWS_];
__device__ __align__(16) __nv_bfloat16 gH[2][(size_t)ROWS_ * H_];   // 2 x 8 MB limbs
__device__ __align__(16) __nv_bfloat16 gW[2][H_ * H_];              // 2 x 128 KB limbs

// ---------------- warp-mma helpers ----------------
__device__ __forceinline__ uint32_t smem_u32(const void* p) {
    uint32_t a;
    asm("{ .reg .u64 t; cvta.to.shared.u64 t, %1; cvt.u32.u64 %0, t; }" : "=r"(a) : "l"(p));
    return a;
}
__device__ __forceinline__ void ldm4(uint32_t* r, uint32_t addr) {
    asm volatile("ldmatrix.sync.aligned.m8n8.x4.shared.b16 {%0,%1,%2,%3}, [%4];"
                 : "=r"(r[0]), "=r"(r[1]), "=r"(r[2]), "=r"(r[3]) : "r"(addr));
}
__device__ __forceinline__ void mma16816(float* c, const uint32_t* a, const uint32_t* b) {
    asm volatile(
        "mma.sync.aligned.m16n8k16.row.col.f32.bf16.bf16.f32 "
        "{%0,%1,%2,%3},{%4,%5,%6,%7},{%8,%9},{%0,%1,%2,%3};"
        : "+f"(c[0]), "+f"(c[1]), "+f"(c[2]), "+f"(c[3])
        : "r"(a[0]), "r"(a[1]), "r"(a[2]), "r"(a[3]), "r"(b[0]), "r"(b[1]));
}

// ---------------- fused conversion: fp32 -> 2 bf16 limbs (W then h) --------
__device__ __forceinline__ void split2(float x, __nv_bfloat16& a, __nv_bfloat16& b) {
    a = __float2bfloat16(x);
    b = __float2bfloat16(x - __bfloat162float(a));
}
__global__ void __launch_bounds__(NT) conv_kernel(const float* __restrict__ h,
                                                  const float* __restrict__ W1) {
    int i = blockIdx.x * NT + threadIdx.x;
    const float* src;
    __nv_bfloat16 *d0, *d1;
    int j;
    if (i < NW2) { src = W1; j = i;        d0 = gW[0]; d1 = gW[1]; }
    else         { src = h;  j = i - NW2;  d0 = gH[0]; d1 = gH[1];
                   if (j >= NH2) return; }
    float2 v = ((const float2*)src)[j];
    __nv_bfloat16 a0, b0, a1, b1;
    split2(v.x, a0, b0);
    split2(v.y, a1, b1);
    *(__nv_bfloat162*)&d0[j * 2] = __nv_bfloat162(a0, a1);
    *(__nv_bfloat162*)&d1[j * 2] = __nv_bfloat162(b0, b1);
}

// ---------------- Phase A: full-N bf16 2-limb mma.sync + fused epilogue -----
// Block: 256 threads (8 warps). Tile M=128 rows x N=256 (ALL cols), K=256 in
// 4 chunks of 64. Warp w owns rows 16w..16w+15 (1 m-tile) x 32 n-tiles.
// 3 limb-products (hi*hi, hi*lo, lo*hi). Epilogue emits complete s -> g_s.
// smem: A[2][128][72], B[2][256][72] halves; stride 72 = conflict-free ldmatrix.
#define AST    72
#define A_LIMB (128 * AST)              // halves
#define B_LIMB (256 * AST)
#define SA_BYTES (2 * A_LIMB * 2)       // 36864
#define SB_BASE  SA_BYTES
#define SMEMSZ (SA_BYTES + 2 * B_LIMB * 2)   // 110592

__global__ void __launch_bounds__(NT, 1) mma_kernel(
    const float* __restrict__ b1, const float* __restrict__ w2)
{
    extern __shared__ char smem[];
    const uint32_t sb = smem_u32(smem);
    const int t = threadIdx.x, wid = t >> 5, lane = t & 31;
    const int rowBase = blockIdx.x * 128;

    // ldmatrix lane addressing
    const int arow = lane & 15, acg = lane >> 4;
    const int brow = (lane & 7) + 8 * (lane >> 4), bcg = (lane >> 3) & 1;
    uint32_t aaddr[2];
#pragma unroll
    for (int s = 0; s < 2; s++)
        aaddr[s] = sb + (s * A_LIMB + (wid * 16 + arow) * AST + acg * 8) * 2;

    float acc[32][4];
#pragma unroll
    for (int nt = 0; nt < 32; nt++)
#pragma unroll
        for (int e = 0; e < 4; e++) acc[nt][e] = 0.f;

#pragma unroll 1
    for (int kc = 0; kc < 4; kc++) {
        // ---- stage chunk kc (single-buffered) ----
        const int ko = kc * 64;
#pragma unroll
        for (int s = 0; s < 2; s++) {
#pragma unroll 4
            for (int u = t; u < 1024; u += NT) {            // A: 128 rows x 8 q
                int row = u >> 3, q = u & 7;
                uint4 v = *(const uint4*)&gH[s][(size_t)(rowBase + row) * H_ + ko + q * 8];
                *(uint4*)(smem + (s * A_LIMB + row * AST + q * 8) * 2) = v;
            }
#pragma unroll 8
            for (int u = t; u < 2048; u += NT) {            // B: 256 cols x 8 q
                int row = u >> 3, q = u & 7;
                uint4 v = *(const uint4*)&gW[s][(size_t)row * H_ + ko + q * 8];
                *(uint4*)(smem + SB_BASE + (s * B_LIMB + row * AST + q * 8) * 2) = v;
            }
        }
        __syncthreads();

#pragma unroll
        for (int ks = 0; ks < 4; ks++) {
            uint32_t a[2][4];
            ldm4(a[0], aaddr[0] + ks * 32);
            ldm4(a[1], aaddr[1] + ks * 32);
#pragma unroll
            for (int ng = 0; ng < 4; ng++) {                // 8 n-tiles per group
                uint32_t b[2][8][2];
#pragma unroll
                for (int s = 0; s < 2; s++)
#pragma unroll
                    for (int p = 0; p < 4; p++) {
                        uint32_t r[4];
                        uint32_t ba = sb + SB_BASE +
                            (s * B_LIMB + (ng * 64 + p * 16 + brow) * AST + bcg * 8 + ks * 16) * 2;
                        ldm4(r, ba);
                        b[s][p * 2][0] = r[0];      b[s][p * 2][1] = r[1];
                        b[s][p * 2 + 1][0] = r[2];  b[s][p * 2 + 1][1] = r[3];
                    }
#pragma unroll
                for (int j = 0; j < 8; j++) {
                    float* c = acc[ng * 8 + j];
                    mma16816(c, a[0], b[0][j]);   // hi*hi
                    mma16816(c, a[0], b[1][j]);   // hi*lo
                    mma16816(c, a[1], b[0][j]);   // lo*hi
                }
            }
        }
        __syncthreads();
    }

    // ---- epilogue: silu(x+b1)*w2 dot over all 256 cols -> complete s ------
    float p0 = 0.f, p1 = 0.f;
#pragma unroll
    for (int nt = 0; nt < 32; nt++) {
        const int c0 = nt * 8 + 2 * (lane & 3);
        const float bb0 = __ldg(b1 + c0), bb1 = __ldg(b1 + c0 + 1);
        const float ww0 = __ldg(w2 + c0), ww1 = __ldg(w2 + c0 + 1);
        float v;
        v = acc[nt][0] + bb0;  p0 += (v / (1.f + __expf(-v))) * ww0;
        v = acc[nt][1] + bb1;  p0 += (v / (1.f + __expf(-v))) * ww1;
        v = acc[nt][2] + bb0;  p1 += (v / (1.f + __expf(-v))) * ww0;
        v = acc[nt][3] + bb1;  p1 += (v / (1.f + __expf(-v))) * ww1;
    }
    p0 += __shfl_xor_sync(0xFFFFFFFF, p0, 1);
    p0 += __shfl_xor_sync(0xFFFFFFFF, p0, 2);
    p1 += __shfl_xor_sync(0xFFFFFFFF, p1, 1);
    p1 += __shfl_xor_sync(0xFFFFFFFF, p1, 2);
    if ((lane & 3) == 0) {
        int row = rowBase + wid * 16 + (lane >> 2);
        g_s[row] = p0;
        g_s[row + 8] = p1;
    }
}

// ---------------- Phase B: out[b,i,j] = truncf(s_i - s_j + b2) as float -----
// (proven R4 config: 1 row/block, 2x LDG.128 + 2x STG.128 per thread)
__global__ void __launch_bounds__(NT) out_kernel(
    const float* __restrict__ b2p, float* __restrict__ out)
{
    const int t = threadIdx.x;
    const int i = blockIdx.x;
    const int b = blockIdx.y;
    const float* sbp = g_s + b * N_;
    const float sib = sbp[i] + __ldg(b2p);
    const int j0 = t * 8;
    float4 p0 = *(const float4*)(sbp + j0);
    float4 p1 = *(const float4*)(sbp + j0 + 4);
    float4 v0, v1;
    v0.x = truncf(sib - p0.x);  v0.y = truncf(sib - p0.y);
    v0.z = truncf(sib - p0.z);  v0.w = truncf(sib - p0.w);
    v1.x = truncf(sib - p1.x);  v1.y = truncf(sib - p1.y);
    v1.z = truncf(sib - p1.z);  v1.w = truncf(sib - p1.w);
    const size_t base = ((size_t)(b * N_ + i)) * N_ + j0;
    *(float4*)(out + base)     = v0;
    *(float4*)(out + base + 4) = v1;
}

extern "C" void kernel_launch(void* const* d_in, const int* in_sizes, int n_in,
                              void* d_out, int out_size)
{
    const float *h = 0, *W1 = 0, *b1 = 0, *w2 = 0, *b2 = 0;
    for (int idx = 0; idx < n_in; ++idx) {
        const int sz = in_sizes[idx];
        if (sz == ROWS_ * H_)      h  = (const float*)d_in[idx];
        else if (sz == H_ * H_)    W1 = (const float*)d_in[idx];
        else if (sz == H_) {
            if (!b1) b1 = (const float*)d_in[idx];
            else if (!w2) w2 = (const float*)d_in[idx];
        }
        else if (sz == 1)          b2 = (const float*)d_in[idx];
    }
    (void)out_size;

    static int attr_set = 0;
    if (!attr_set) {
        cudaFuncSetAttribute(mma_kernel, cudaFuncAttributeMaxDynamicSharedMemorySize, SMEMSZ);
        attr_set = 1;
    }

    conv_kernel<<<(NW2 + NH2 + NT - 1) / NT, NT>>>(h, W1);
    mma_kernel<<<ROWS_ / 128, NT, SMEMSZ>>>(b1, w2);
    out_kernel<<<dim3(N_, B_), NT>>>(b2, (float*)d_out);
}

// round 10
// speedup vs baseline: 1.3584x; 1.0043x over previous
#include <cuda_runtime.h>
#include <cuda_bf16.h>
#include <math.h>
#include <stdint.h>

#define B_    8
#define N_    2048
#define H_    256
#define ROWS_ (B_ * N_)
#define NT    256

// ---------------- device scratch ----------------
__device__ float g_s[ROWS_];

// ---------------- warp-mma helpers ----------------
__device__ __forceinline__ uint32_t smem_u32(const void* p) {
    uint32_t a;
    asm("{ .reg .u64 t; cvta.to.shared.u64 t, %1; cvt.u32.u64 %0, t; }" : "=r"(a) : "l"(p));
    return a;
}
__device__ __forceinline__ void ldm4(uint32_t* r, uint32_t addr) {
    asm volatile("ldmatrix.sync.aligned.m8n8.x4.shared.b16 {%0,%1,%2,%3}, [%4];"
                 : "=r"(r[0]), "=r"(r[1]), "=r"(r[2]), "=r"(r[3]) : "r"(addr));
}
__device__ __forceinline__ void mma16816(float* c, const uint32_t* a, const uint32_t* b) {
    asm volatile(
        "mma.sync.aligned.m16n8k16.row.col.f32.bf16.bf16.f32 "
        "{%0,%1,%2,%3},{%4,%5,%6,%7},{%8,%9},{%0,%1,%2,%3};"
        : "+f"(c[0]), "+f"(c[1]), "+f"(c[2]), "+f"(c[3])
        : "r"(a[0]), "r"(a[1]), "r"(a[2]), "r"(a[3]), "r"(b[0]), "r"(b[1]));
}

// split a float4 into hi-limb (4 bf16 packed in uint2) and lo-limb
__device__ __forceinline__ void split4(float4 v, uint2& hi, uint2& lo) {
    __nv_bfloat162 h0 = __nv_bfloat162(__float2bfloat16(v.x), __float2bfloat16(v.y));
    __nv_bfloat162 h1 = __nv_bfloat162(__float2bfloat16(v.z), __float2bfloat16(v.w));
    __nv_bfloat162 l0 = __nv_bfloat162(
        __float2bfloat16(v.x - __bfloat162float(h0.x)),
        __float2bfloat16(v.y - __bfloat162float(h0.y)));
    __nv_bfloat162 l1 = __nv_bfloat162(
        __float2bfloat16(v.z - __bfloat162float(h1.x)),
        __float2bfloat16(v.w - __bfloat162float(h1.y)));
    hi.x = *(uint32_t*)&h0;  hi.y = *(uint32_t*)&h1;
    lo.x = *(uint32_t*)&l0;  lo.y = *(uint32_t*)&l1;
}

// ---------------- Phase A: fused split + full-N bf16 2-limb mma.sync --------
// Block: 256 threads (8 warps). Tile M=128 rows x N=256 (all cols), K=256 in
// 4 chunks of 64. Staging loads fp32 h/W1 and splits to bf16 limbs in-flight
// (same global bytes as limb arrays; kills the separate conv pass).
// Warp w owns rows 16w..16w+15 x 32 n-tiles; 3 limb-products per position.
#define AST    72
#define A_LIMB (128 * AST)              // halves
#define B_LIMB (256 * AST)
#define SA_BYTES (2 * A_LIMB * 2)       // 36864
#define SB_BASE  SA_BYTES
#define SMEMSZ (SA_BYTES + 2 * B_LIMB * 2)   // 110592

__global__ void __launch_bounds__(NT, 1) mma_kernel(
    const float* __restrict__ h, const float* __restrict__ W1,
    const float* __restrict__ b1, const float* __restrict__ w2)
{
    extern __shared__ char smem[];
    const uint32_t sb = smem_u32(smem);
    const int t = threadIdx.x, wid = t >> 5, lane = t & 31;
    const int rowBase = blockIdx.x * 128;

    const int arow = lane & 15, acg = lane >> 4;
    const int brow = (lane & 7) + 8 * (lane >> 4), bcg = (lane >> 3) & 1;
    uint32_t aaddr[2];
#pragma unroll
    for (int s = 0; s < 2; s++)
        aaddr[s] = sb + (s * A_LIMB + (wid * 16 + arow) * AST + acg * 8) * 2;

    float acc[32][4];
#pragma unroll
    for (int nt = 0; nt < 32; nt++)
#pragma unroll
        for (int e = 0; e < 4; e++) acc[nt][e] = 0.f;

#pragma unroll 1
    for (int kc = 0; kc < 4; kc++) {
        const int ko = kc * 64;
        // ---- stage A: 128 rows x 64 k fp32 -> 2 limb tiles (2048 float4) --
#pragma unroll 4
        for (int u = t; u < 2048; u += NT) {
            int row = u >> 4, q = u & 15;                   // q: 4-float group
            float4 v = *(const float4*)&h[(size_t)(rowBase + row) * H_ + ko + q * 4];
            uint2 hi, lo;
            split4(v, hi, lo);
            char* dst = smem + (row * AST + q * 4) * 2;
            *(uint2*)(dst) = hi;
            *(uint2*)(dst + A_LIMB * 2) = lo;
        }
        // ---- stage B: 256 cols x 64 k fp32 -> 2 limb tiles (4096 float4) --
#pragma unroll 8
        for (int u = t; u < 4096; u += NT) {
            int row = u >> 4, q = u & 15;
            float4 v = *(const float4*)&W1[(size_t)row * H_ + ko + q * 4];
            uint2 hi, lo;
            split4(v, hi, lo);
            char* dst = smem + SB_BASE + (row * AST + q * 4) * 2;
            *(uint2*)(dst) = hi;
            *(uint2*)(dst + B_LIMB * 2) = lo;
        }
        __syncthreads();

#pragma unroll
        for (int ks = 0; ks < 4; ks++) {
            uint32_t a[2][4];
            ldm4(a[0], aaddr[0] + ks * 32);
            ldm4(a[1], aaddr[1] + ks * 32);
#pragma unroll
            for (int ng = 0; ng < 4; ng++) {
                uint32_t b[2][8][2];
#pragma unroll
                for (int s = 0; s < 2; s++)
#pragma unroll
                    for (int p = 0; p < 4; p++) {
                        uint32_t r[4];
                        uint32_t ba = sb + SB_BASE +
                            (s * B_LIMB + (ng * 64 + p * 16 + brow) * AST + bcg * 8 + ks * 16) * 2;
                        ldm4(r, ba);
                        b[s][p * 2][0] = r[0];      b[s][p * 2][1] = r[1];
                        b[s][p * 2 + 1][0] = r[2];  b[s][p * 2 + 1][1] = r[3];
                    }
#pragma unroll
                for (int j = 0; j < 8; j++) {
                    float* c = acc[ng * 8 + j];
                    mma16816(c, a[0], b[0][j]);   // hi*hi
                    mma16816(c, a[0], b[1][j]);   // hi*lo
                    mma16816(c, a[1], b[0][j]);   // lo*hi
                }
            }
        }
        __syncthreads();
    }

    // ---- epilogue: silu(x+b1)*w2 dot over all 256 cols -> complete s ------
    float p0 = 0.f, p1 = 0.f;
#pragma unroll
    for (int nt = 0; nt < 32; nt++) {
        const int c0 = nt * 8 + 2 * (lane & 3);
        const float bb0 = __ldg(b1 + c0), bb1 = __ldg(b1 + c0 + 1);
        const float ww0 = __ldg(w2 + c0), ww1 = __ldg(w2 + c0 + 1);
        float v;
        v = acc[nt][0] + bb0;  p0 += (v / (1.f + __expf(-v))) * ww0;
        v = acc[nt][1] + bb1;  p0 += (v / (1.f + __expf(-v))) * ww1;
        v = acc[nt][2] + bb0;  p1 += (v / (1.f + __expf(-v))) * ww0;
        v = acc[nt][3] + bb1;  p1 += (v / (1.f + __expf(-v))) * ww1;
    }
    p0 += __shfl_xor_sync(0xFFFFFFFF, p0, 1);
    p0 += __shfl_xor_sync(0xFFFFFFFF, p0, 2);
    p1 += __shfl_xor_sync(0xFFFFFFFF, p1, 1);
    p1 += __shfl_xor_sync(0xFFFFFFFF, p1, 2);
    if ((lane & 3) == 0) {
        int row = rowBase + wid * 16 + (lane >> 2);
        g_s[row] = p0;
        g_s[row + 8] = p1;
    }
}

// ---------------- Phase B: out[b,i,j] = truncf(s_i - s_j + b2) as float -----
__global__ void __launch_bounds__(NT) out_kernel(
    const float* __restrict__ b2p, float* __restrict__ out)
{
    const int t = threadIdx.x;
    const int i = blockIdx.x;
    const int b = blockIdx.y;
    const float* sbp = g_s + b * N_;
    const float sib = sbp[i] + __ldg(b2p);
    const int j0 = t * 8;
    float4 p0 = *(const float4*)(sbp + j0);
    float4 p1 = *(const float4*)(sbp + j0 + 4);
    float4 v0, v1;
    v0.x = truncf(sib - p0.x);  v0.y = truncf(sib - p0.y);
    v0.z = truncf(sib - p0.z);  v0.w = truncf(sib - p0.w);
    v1.x = truncf(sib - p1.x);  v1.y = truncf(sib - p1.y);
    v1.z = truncf(sib - p1.z);  v1.w = truncf(sib - p1.w);
    const size_t base = ((size_t)(b * N_ + i)) * N_ + j0;
    *(float4*)(out + base)     = v0;
    *(float4*)(out + base + 4) = v1;
}

extern "C" void kernel_launch(void* const* d_in, const int* in_sizes, int n_in,
                              void* d_out, int out_size)
{
    const float *h = 0, *W1 = 0, *b1 = 0, *w2 = 0, *b2 = 0;
    for (int idx = 0; idx < n_in; ++idx) {
        const int sz = in_sizes[idx];
        if (sz == ROWS_ * H_)      h  = (const float*)d_in[idx];
        else if (sz == H_ * H_)    W1 = (const float*)d_in[idx];
        else if (sz == H_) {
            if (!b1) b1 = (const float*)d_in[idx];
            else if (!w2) w2 = (const float*)d_in[idx];
        }
        else if (sz == 1)          b2 = (const float*)d_in[idx];
    }
    (void)out_size;

    static int attr_set = 0;
    if (!attr_set) {
        cudaFuncSetAttribute(mma_kernel, cudaFuncAttributeMaxDynamicSharedMemorySize, SMEMSZ);
        attr_set = 1;
    }

    mma_kernel<<<ROWS_ / 128, NT, SMEMSZ>>>(h, W1, b1, w2);
    out_kernel<<<dim3(N_, B_), NT>>>(b2, (float*)d_out);
}

// round 11
// speedup vs baseline: 1.3878x; 1.0216x over previous
#include <cuda_runtime.h>
#include <cuda_bf16.h>
#include <math.h>
#include <stdint.h>

#define B_    8
#define N_    2048
#define H_    256
#define ROWS_ (B_ * N_)
#define NT    256

// ---------------- device scratch ----------------
__device__ float g_s[ROWS_];
__device__ __align__(16) __nv_bfloat16 gW[2][H_ * H_];   // W1 limbs, split once

// ---------------- warp-mma helpers ----------------
__device__ __forceinline__ uint32_t smem_u32(const void* p) {
    uint32_t a;
    asm("{ .reg .u64 t; cvta.to.shared.u64 t, %1; cvt.u32.u64 %0, t; }" : "=r"(a) : "l"(p));
    return a;
}
__device__ __forceinline__ void ldm4(uint32_t* r, uint32_t addr) {
    asm volatile("ldmatrix.sync.aligned.m8n8.x4.shared.b16 {%0,%1,%2,%3}, [%4];"
                 : "=r"(r[0]), "=r"(r[1]), "=r"(r[2]), "=r"(r[3]) : "r"(addr));
}
__device__ __forceinline__ void mma16816(float* c, const uint32_t* a, const uint32_t* b) {
    asm volatile(
        "mma.sync.aligned.m16n8k16.row.col.f32.bf16.bf16.f32 "
        "{%0,%1,%2,%3},{%4,%5,%6,%7},{%8,%9},{%0,%1,%2,%3};"
        : "+f"(c[0]), "+f"(c[1]), "+f"(c[2]), "+f"(c[3])
        : "r"(a[0]), "r"(a[1]), "r"(a[2]), "r"(a[3]), "r"(b[0]), "r"(b[1]));
}

// split a float4 into hi-limb (4 bf16 in uint2) and lo-limb
__device__ __forceinline__ void split4(float4 v, uint2& hi, uint2& lo) {
    __nv_bfloat162 h0 = __nv_bfloat162(__float2bfloat16(v.x), __float2bfloat16(v.y));
    __nv_bfloat162 h1 = __nv_bfloat162(__float2bfloat16(v.z), __float2bfloat16(v.w));
    __nv_bfloat162 l0 = __nv_bfloat162(
        __float2bfloat16(v.x - __bfloat162float(h0.x)),
        __float2bfloat16(v.y - __bfloat162float(h0.y)));
    __nv_bfloat162 l1 = __nv_bfloat162(
        __float2bfloat16(v.z - __bfloat162float(h1.x)),
        __float2bfloat16(v.w - __bfloat162float(h1.y)));
    hi.x = *(uint32_t*)&h0;  hi.y = *(uint32_t*)&h1;
    lo.x = *(uint32_t*)&l0;  lo.y = *(uint32_t*)&l1;
}

// ---------------- conv_w: split W1 ONCE into gW limbs (128 KB -> 2x128 KB) --
__global__ void __launch_bounds__(NT) conv_w(const float* __restrict__ W1) {
    int i = blockIdx.x * NT + threadIdx.x;            // one float4 per thread
    float4 v = ((const float4*)W1)[i];
    uint2 hi, lo;
    split4(v, hi, lo);
    *(uint2*)&gW[0][i * 4] = hi;
    *(uint2*)&gW[1][i * 4] = lo;
}

// ---------------- Phase A: full-N bf16 2-limb mma.sync ----------------------
// Block: 256 threads (8 warps). Tile M=128 x N=256 (all cols), K=256 in 4x64.
// A staged with fused fp32->limb split (each h element split exactly once);
// B staged as pure uint4 copies from precomputed gW limbs (no CVT).
// Warp w owns rows 16w..16w+15 x 32 n-tiles; 3 limb-products per position.
#define AST    72
#define A_LIMB (128 * AST)              // halves
#define B_LIMB (256 * AST)
#define SA_BYTES (2 * A_LIMB * 2)       // 36864
#define SB_BASE  SA_BYTES
#define SMEMSZ (SA_BYTES + 2 * B_LIMB * 2)   // 110592

__global__ void __launch_bounds__(NT, 1) mma_kernel(
    const float* __restrict__ h, const float* __restrict__ b1,
    const float* __restrict__ w2)
{
    extern __shared__ char smem[];
    const uint32_t sb = smem_u32(smem);
    const int t = threadIdx.x, wid = t >> 5, lane = t & 31;
    const int rowBase = blockIdx.x * 128;

    const int arow = lane & 15, acg = lane >> 4;
    const int brow = (lane & 7) + 8 * (lane >> 4), bcg = (lane >> 3) & 1;
    uint32_t aaddr[2];
#pragma unroll
    for (int s = 0; s < 2; s++)
        aaddr[s] = sb + (s * A_LIMB + (wid * 16 + arow) * AST + acg * 8) * 2;

    float acc[32][4];
#pragma unroll
    for (int nt = 0; nt < 32; nt++)
#pragma unroll
        for (int e = 0; e < 4; e++) acc[nt][e] = 0.f;

#pragma unroll 1
    for (int kc = 0; kc < 4; kc++) {
        const int ko = kc * 64;
        // ---- stage A: 128 rows x 64 k fp32 -> split -> 2 limb tiles -------
#pragma unroll 4
        for (int u = t; u < 2048; u += NT) {
            int row = u >> 4, q = u & 15;
            float4 v = *(const float4*)&h[(size_t)(rowBase + row) * H_ + ko + q * 4];
            uint2 hi, lo;
            split4(v, hi, lo);
            char* dst = smem + (row * AST + q * 4) * 2;
            *(uint2*)(dst) = hi;
            *(uint2*)(dst + A_LIMB * 2) = lo;
        }
        // ---- stage B: pure copy of gW limb tiles (2 x 2048 uint4) ---------
#pragma unroll
        for (int s = 0; s < 2; s++) {
#pragma unroll 8
            for (int u = t; u < 2048; u += NT) {          // 256 rows x 8 q
                int row = u >> 3, q = u & 7;
                uint4 v = *(const uint4*)&gW[s][(size_t)row * H_ + ko + q * 8];
                *(uint4*)(smem + SB_BASE + (s * B_LIMB + row * AST + q * 8) * 2) = v;
            }
        }
        __syncthreads();

#pragma unroll
        for (int ks = 0; ks < 4; ks++) {
            uint32_t a[2][4];
            ldm4(a[0], aaddr[0] + ks * 32);
            ldm4(a[1], aaddr[1] + ks * 32);
#pragma unroll
            for (int ng = 0; ng < 4; ng++) {
                uint32_t b[2][8][2];
#pragma unroll
                for (int s = 0; s < 2; s++)
#pragma unroll
                    for (int p = 0; p < 4; p++) {
                        uint32_t r[4];
                        uint32_t ba = sb + SB_BASE +
                            (s * B_LIMB + (ng * 64 + p * 16 + brow) * AST + bcg * 8 + ks * 16) * 2;
                        ldm4(r, ba);
                        b[s][p * 2][0] = r[0];      b[s][p * 2][1] = r[1];
                        b[s][p * 2 + 1][0] = r[2];  b[s][p * 2 + 1][1] = r[3];
                    }
#pragma unroll
                for (int j = 0; j < 8; j++) {
                    float* c = acc[ng * 8 + j];
                    mma16816(c, a[0], b[0][j]);   // hi*hi
                    mma16816(c, a[0], b[1][j]);   // hi*lo
                    mma16816(c, a[1], b[0][j]);   // lo*hi
                }
            }
        }
        __syncthreads();
    }

    // ---- epilogue: silu(x+b1)*w2 dot over all 256 cols -> complete s ------
    float p0 = 0.f, p1 = 0.f;
#pragma unroll
    for (int nt = 0; nt < 32; nt++) {
        const int c0 = nt * 8 + 2 * (lane & 3);
        const float bb0 = __ldg(b1 + c0), bb1 = __ldg(b1 + c0 + 1);
        const float ww0 = __ldg(w2 + c0), ww1 = __ldg(w2 + c0 + 1);
        float v;
        v = acc[nt][0] + bb0;  p0 += (v / (1.f + __expf(-v))) * ww0;
        v = acc[nt][1] + bb1;  p0 += (v / (1.f + __expf(-v))) * ww1;
        v = acc[nt][2] + bb0;  p1 += (v / (1.f + __expf(-v))) * ww0;
        v = acc[nt][3] + bb1;  p1 += (v / (1.f + __expf(-v))) * ww1;
    }
    p0 += __shfl_xor_sync(0xFFFFFFFF, p0, 1);
    p0 += __shfl_xor_sync(0xFFFFFFFF, p0, 2);
    p1 += __shfl_xor_sync(0xFFFFFFFF, p1, 1);
    p1 += __shfl_xor_sync(0xFFFFFFFF, p1, 2);
    if ((lane & 3) == 0) {
        int row = rowBase + wid * 16 + (lane >> 2);
        g_s[row] = p0;
        g_s[row + 8] = p1;
    }
}

// ---------------- Phase B: out[b,i,j] = truncf(s_i - s_j + b2) as float -----
__global__ void __launch_bounds__(NT) out_kernel(
    const float* __restrict__ b2p, float* __restrict__ out)
{
    const int t = threadIdx.x;
    const int i = blockIdx.x;
    const int b = blockIdx.y;
    const float* sbp = g_s + b * N_;
    const float sib = sbp[i] + __ldg(b2p);
    const int j0 = t * 8;
    float4 p0 = *(const float4*)(sbp + j0);
    float4 p1 = *(const float4*)(sbp + j0 + 4);
    float4 v0, v1;
    v0.x = truncf(sib - p0.x);  v0.y = truncf(sib - p0.y);
    v0.z = truncf(sib - p0.z);  v0.w = truncf(sib - p0.w);
    v1.x = truncf(sib - p1.x);  v1.y = truncf(sib - p1.y);
    v1.z = truncf(sib - p1.z);  v1.w = truncf(sib - p1.w);
    const size_t base = ((size_t)(b * N_ + i)) * N_ + j0;
    *(float4*)(out + base)     = v0;
    *(float4*)(out + base + 4) = v1;
}

extern "C" void kernel_launch(void* const* d_in, const int* in_sizes, int n_in,
                              void* d_out, int out_size)
{
    const float *h = 0, *W1 = 0, *b1 = 0, *w2 = 0, *b2 = 0;
    for (int idx = 0; idx < n_in; ++idx) {
        const int sz = in_sizes[idx];
        if (sz == ROWS_ * H_)      h  = (const float*)d_in[idx];
        else if (sz == H_ * H_)    W1 = (const float*)d_in[idx];
        else if (sz == H_) {
            if (!b1) b1 = (const float*)d_in[idx];
            else if (!w2) w2 = (const float*)d_in[idx];
        }
        else if (sz == 1)          b2 = (const float*)d_in[idx];
    }
    (void)out_size;

    static int attr_set = 0;
    if (!attr_set) {
        cudaFuncSetAttribute(mma_kernel, cudaFuncAttributeMaxDynamicSharedMemorySize, SMEMSZ);
        attr_set = 1;
    }

    conv_w<<<H_ * H_ / 4 / NT, NT>>>(W1);                  // 64 blocks
    mma_kernel<<<ROWS_ / 128, NT, SMEMSZ>>>(h, b1, w2);
    out_kernel<<<dim3(N_, B_), NT>>>(b2, (float*)d_out);
}

// round 12
// speedup vs baseline: 1.4076x; 1.0142x over previous
#include <cuda_runtime.h>
#include <cuda_bf16.h>
#include <math.h>
#include <stdint.h>

#define B_    8
#define N_    2048
#define H_    256
#define ROWS_ (B_ * N_)
#define NT    256

// ---------------- device scratch ----------------
__device__ float g_s[ROWS_];
__device__ __align__(16) __nv_bfloat16 gW[2][H_ * H_];   // W1 limbs, split once

// ---------------- helpers ----------------
__device__ __forceinline__ uint32_t smem_u32(const void* p) {
    uint32_t a;
    asm("{ .reg .u64 t; cvta.to.shared.u64 t, %1; cvt.u32.u64 %0, t; }" : "=r"(a) : "l"(p));
    return a;
}
__device__ __forceinline__ void ldm4(uint32_t* r, uint32_t addr) {
    asm volatile("ldmatrix.sync.aligned.m8n8.x4.shared.b16 {%0,%1,%2,%3}, [%4];"
                 : "=r"(r[0]), "=r"(r[1]), "=r"(r[2]), "=r"(r[3]) : "r"(addr));
}
__device__ __forceinline__ void mma16816(float* c, const uint32_t* a, const uint32_t* b) {
    asm volatile(
        "mma.sync.aligned.m16n8k16.row.col.f32.bf16.bf16.f32 "
        "{%0,%1,%2,%3},{%4,%5,%6,%7},{%8,%9},{%0,%1,%2,%3};"
        : "+f"(c[0]), "+f"(c[1]), "+f"(c[2]), "+f"(c[3])
        : "r"(a[0]), "r"(a[1]), "r"(a[2]), "r"(a[3]), "r"(b[0]), "r"(b[1]));
}
__device__ __forceinline__ void cp16(uint32_t saddr, const void* gaddr) {
    asm volatile("cp.async.cg.shared.global [%0], [%1], 16;" :: "r"(saddr), "l"(gaddr));
}
#define CP_COMMIT() asm volatile("cp.async.commit_group;" ::: "memory")
#define CP_WAIT0()  asm volatile("cp.async.wait_group 0;" ::: "memory")

// split a float4 into hi-limb (4 bf16 in uint2) and lo-limb
__device__ __forceinline__ void split4(float4 v, uint2& hi, uint2& lo) {
    __nv_bfloat162 h0 = __nv_bfloat162(__float2bfloat16(v.x), __float2bfloat16(v.y));
    __nv_bfloat162 h1 = __nv_bfloat162(__float2bfloat16(v.z), __float2bfloat16(v.w));
    __nv_bfloat162 l0 = __nv_bfloat162(
        __float2bfloat16(v.x - __bfloat162float(h0.x)),
        __float2bfloat16(v.y - __bfloat162float(h0.y)));
    __nv_bfloat162 l1 = __nv_bfloat162(
        __float2bfloat16(v.z - __bfloat162float(h1.x)),
        __float2bfloat16(v.w - __bfloat162float(h1.y)));
    hi.x = *(uint32_t*)&h0;  hi.y = *(uint32_t*)&h1;
    lo.x = *(uint32_t*)&l0;  lo.y = *(uint32_t*)&l1;
}

// ---------------- conv_w: split W1 ONCE into gW limbs ----------------------
__global__ void __launch_bounds__(NT) conv_w(const float* __restrict__ W1) {
    int i = blockIdx.x * NT + threadIdx.x;            // one float4 per thread
    float4 v = ((const float4*)W1)[i];
    uint2 hi, lo;
    split4(v, hi, lo);
    *(uint2*)&gW[0][i * 4] = hi;
    *(uint2*)&gW[1][i * 4] = lo;
}

// ---------------- Phase A: double-buffered bf16 2-limb mma.sync -------------
// Block: 256 threads / 8 warps. M=128 x N=256 (all cols), K=256 in 4x64.
// Double-buffered: A (fused fp32->limb split, STS) and B (cp.async of gW
// limbs) for chunk kc+1 are staged while chunk kc computes. 1 sync/chunk.
#define AST    72
#define A_LIMB (128 * AST)                 // halves
#define B_LIMB (256 * AST)
#define A_BYTES (2 * A_LIMB * 2)           // 36864
#define B_BYTES (2 * B_LIMB * 2)           // 73728
#define SB_BASE (2 * A_BYTES)              // 73728
#define SMEMSZ  (2 * A_BYTES + 2 * B_BYTES)   // 221184

__global__ void __launch_bounds__(NT, 1) mma_kernel(
    const float* __restrict__ h, const float* __restrict__ b1,
    const float* __restrict__ w2)
{
    extern __shared__ char smem[];
    const uint32_t sb = smem_u32(smem);
    const int t = threadIdx.x, wid = t >> 5, lane = t & 31;
    const int rowBase = blockIdx.x * 128;

    const int arow = lane & 15, acg = lane >> 4;
    const int brow = (lane & 7) + 8 * (lane >> 4), bcg = (lane >> 3) & 1;

    float acc[32][4];
#pragma unroll
    for (int nt = 0; nt < 32; nt++)
#pragma unroll
        for (int e = 0; e < 4; e++) acc[nt][e] = 0.f;

    // ---- staging helpers (buffer bu, k-offset ko) ----
    auto stageA = [&](int bu, int ko) {
        char* base = smem + bu * A_BYTES;
#pragma unroll 4
        for (int u = t; u < 2048; u += NT) {
            int row = u >> 4, q = u & 15;
            float4 v = *(const float4*)&h[(size_t)(rowBase + row) * H_ + ko + q * 4];
            uint2 hi, lo;
            split4(v, hi, lo);
            char* dst = base + (row * AST + q * 4) * 2;
            *(uint2*)(dst) = hi;
            *(uint2*)(dst + A_LIMB * 2) = lo;
        }
    };
    auto stageB = [&](int bu, int ko) {
        uint32_t base = sb + SB_BASE + bu * B_BYTES;
#pragma unroll
        for (int s = 0; s < 2; s++)
#pragma unroll 8
            for (int u = t; u < 2048; u += NT) {          // 256 rows x 8 q
                int row = u >> 3, q = u & 7;
                cp16(base + (s * B_LIMB + row * AST + q * 8) * 2,
                     &gW[s][(size_t)row * H_ + ko + q * 8]);
            }
        CP_COMMIT();
    };

    // ---- prologue: stage chunk 0 ----
    stageB(0, 0);
    stageA(0, 0);
    CP_WAIT0();
    __syncthreads();

#pragma unroll 1
    for (int kc = 0; kc < 4; kc++) {
        // stage next chunk into the other buffer (overlaps compute below)
        if (kc < 3) {
            stageB((kc + 1) & 1, (kc + 1) * 64);
            stageA((kc + 1) & 1, (kc + 1) * 64);
        }

        // ---- compute chunk kc from buffer kc&1 ----
        const uint32_t abase = sb + (kc & 1) * A_BYTES;
        const uint32_t bbase = sb + SB_BASE + (kc & 1) * B_BYTES;
        uint32_t aaddr[2];
#pragma unroll
        for (int s = 0; s < 2; s++)
            aaddr[s] = abase + (s * A_LIMB + (wid * 16 + arow) * AST + acg * 8) * 2;

#pragma unroll
        for (int ks = 0; ks < 4; ks++) {
            uint32_t a[2][4];
            ldm4(a[0], aaddr[0] + ks * 32);
            ldm4(a[1], aaddr[1] + ks * 32);
#pragma unroll
            for (int ng = 0; ng < 4; ng++) {
                uint32_t b[2][8][2];
#pragma unroll
                for (int s = 0; s < 2; s++)
#pragma unroll
                    for (int p = 0; p < 4; p++) {
                        uint32_t r[4];
                        uint32_t ba = bbase +
                            (s * B_LIMB + (ng * 64 + p * 16 + brow) * AST + bcg * 8 + ks * 16) * 2;
                        ldm4(r, ba);
                        b[s][p * 2][0] = r[0];      b[s][p * 2][1] = r[1];
                        b[s][p * 2 + 1][0] = r[2];  b[s][p * 2 + 1][1] = r[3];
                    }
#pragma unroll
                for (int j = 0; j < 8; j++) {
                    float* c = acc[ng * 8 + j];
                    mma16816(c, a[0], b[0][j]);   // hi*hi
                    mma16816(c, a[0], b[1][j]);   // hi*lo
                    mma16816(c, a[1], b[0][j]);   // lo*hi
                }
            }
        }
        if (kc < 3) {
            CP_WAIT0();
            __syncthreads();
        }
    }

    // ---- epilogue: silu(x+b1)*w2 dot over all 256 cols -> complete s ------
    float p0 = 0.f, p1 = 0.f;
#pragma unroll
    for (int nt = 0; nt < 32; nt++) {
        const int c0 = nt * 8 + 2 * (lane & 3);
        const float bb0 = __ldg(b1 + c0), bb1 = __ldg(b1 + c0 + 1);
        const float ww0 = __ldg(w2 + c0), ww1 = __ldg(w2 + c0 + 1);
        float v;
        v = acc[nt][0] + bb0;  p0 += (v / (1.f + __expf(-v))) * ww0;
        v = acc[nt][1] + bb1;  p0 += (v / (1.f + __expf(-v))) * ww1;
        v = acc[nt][2] + bb0;  p1 += (v / (1.f + __expf(-v))) * ww0;
        v = acc[nt][3] + bb1;  p1 += (v / (1.f + __expf(-v))) * ww1;
    }
    p0 += __shfl_xor_sync(0xFFFFFFFF, p0, 1);
    p0 += __shfl_xor_sync(0xFFFFFFFF, p0, 2);
    p1 += __shfl_xor_sync(0xFFFFFFFF, p1, 1);
    p1 += __shfl_xor_sync(0xFFFFFFFF, p1, 2);
    if ((lane & 3) == 0) {
        int row = rowBase + wid * 16 + (lane >> 2);
        g_s[row] = p0;
        g_s[row + 8] = p1;
    }
}

// ---------------- Phase B: out[b,i,j] = truncf(s_i - s_j + b2) as float -----
__global__ void __launch_bounds__(NT) out_kernel(
    const float* __restrict__ b2p, float* __restrict__ out)
{
    const int t = threadIdx.x;
    const int i = blockIdx.x;
    const int b = blockIdx.y;
    const float* sbp = g_s + b * N_;
    const float sib = sbp[i] + __ldg(b2p);
    const int j0 = t * 8;
    float4 p0 = *(const float4*)(sbp + j0);
    float4 p1 = *(const float4*)(sbp + j0 + 4);
    float4 v0, v1;
    v0.x = truncf(sib - p0.x);  v0.y = truncf(sib - p0.y);
    v0.z = truncf(sib - p0.z);  v0.w = truncf(sib - p0.w);
    v1.x = truncf(sib - p1.x);  v1.y = truncf(sib - p1.y);
    v1.z = truncf(sib - p1.z);  v1.w = truncf(sib - p1.w);
    const size_t base = ((size_t)(b * N_ + i)) * N_ + j0;
    *(float4*)(out + base)     = v0;
    *(float4*)(out + base + 4) = v1;
}

extern "C" void kernel_launch(void* const* d_in, const int* in_sizes, int n_in,
                              void* d_out, int out_size)
{
    const float *h = 0, *W1 = 0, *b1 = 0, *w2 = 0, *b2 = 0;
    for (int idx = 0; idx < n_in; ++idx) {
        const int sz = in_sizes[idx];
        if (sz == ROWS_ * H_)      h  = (const float*)d_in[idx];
        else if (sz == H_ * H_)    W1 = (const float*)d_in[idx];
        else if (sz == H_) {
            if (!b1) b1 = (const float*)d_in[idx];
            else if (!w2) w2 = (const float*)d_in[idx];
        }
        else if (sz == 1)          b2 = (const float*)d_in[idx];
    }
    (void)out_size;

    static int attr_set = 0;
    if (!attr_set) {
        cudaFuncSetAttribute(mma_kernel, cudaFuncAttributeMaxDynamicSharedMemorySize, SMEMSZ);
        attr_set = 1;
    }

    conv_w<<<H_ * H_ / 4 / NT, NT>>>(W1);                  // 64 blocks
    mma_kernel<<<ROWS_ / 128, NT, SMEMSZ>>>(h, b1, w2);
    out_kernel<<<dim3(N_, B_), NT>>>(b2, (float*)d_out);
}